// round 15
// baseline (speedup 1.0000x reference)
#include <cuda_runtime.h>
#include <math.h>

#define B_SETS 65536
#define P      22
#define INF_   6
#define HID    64
#define OUTD   128

#define WPB     8
#define THREADS (WPB * 32)
#define GRID    592                 // 148 SMs * 4 blocks/SM
#define S       4
#define NCHUNKS (B_SETS / S)        // 16384
#define NWARPS  (GRID * WPB)        // 4736
#define BASE_CHUNKS (NWARPS * 3)    // 14208 ; tail = 2176 = NWARPS*17/37

__device__ __forceinline__ unsigned long long pack2(float lo, float hi) {
    unsigned long long r;
    asm("mov.b64 %0, {%1,%2};" : "=l"(r) : "f"(lo), "f"(hi));
    return r;
}
__device__ __forceinline__ unsigned long long fma2(unsigned long long a,
                                                   unsigned long long b,
                                                   unsigned long long c) {
    unsigned long long d;
    asm("fma.rn.f32x2 %0, %1, %2, %3;" : "=l"(d) : "l"(a), "l"(b), "l"(c));
    return d;
}

// fast atan2: minimax deg-11 odd poly on [0,1], abs err ~1e-6 (output tol 1e-3)
__device__ __forceinline__ float fast_atan2(float y, float x) {
    const float ax = fabsf(x), ay = fabsf(y);
    const float mx = fmaxf(ax, ay), mn = fminf(ax, ay);
    float t = (mx > 0.f) ? __fdividef(mn, mx) : 0.f;
    const float a = t * t;
    float p = fmaf(a, -0.01172120f, 0.05265332f);
    p = fmaf(a, p, -0.11643287f);
    p = fmaf(a, p,  0.19354346f);
    p = fmaf(a, p, -0.33262347f);
    p = fmaf(a, p,  0.99997726f);
    float r = t * p;
    if (ay > ax)  r = 1.57079632679f - r;
    if (x < 0.f)  r = 3.14159265359f - r;
    return (y < 0.f) ? -r : r;
}

__global__ __launch_bounds__(THREADS, 4)
void set_encoder_kernel(const float* __restrict__ player_locs,
                        const float* __restrict__ actor_locs,
                        const float* __restrict__ flags,
                        const int*   __restrict__ mask,
                        const float* __restrict__ W1,
                        const float* __restrict__ b1,
                        const float* __restrict__ W2,
                        const float* __restrict__ b2,
                        float*       __restrict__ out)
{
    __shared__ float  sW2[HID * OUTD];            // 32 KB
    __shared__ float2 shd[WPB][HID][S];           // pooled hidden, DUPLICATED (h,h)
    __shared__ float4 sf0[WPB][P];                // dx,dy,dist,angle
    __shared__ float2 sf1[WPB][P];                // teammate,keeper

    const int tid  = threadIdx.x;
    const int lane = tid & 31;
    const int wip  = tid >> 5;

    {   // stage W2 into shared once per block
        const float4* W2v  = (const float4*)W2;
        float4*       sW2v = (float4*)sW2;
        #pragma unroll
        for (int i = tid; i < HID * OUTD / 4; i += THREADS) sW2v[i] = W2v[i];
    }

    // W1 columns (lane, lane+32) in registers
    float w1a[INF_], w1b[INF_];
    #pragma unroll
    for (int i = 0; i < INF_; i++) {
        w1a[i] = W1[i * HID + lane];
        w1b[i] = W1[i * HID + lane + 32];
    }
    const float b1a = b1[lane];
    const float b1b = b1[lane + 32];
    float bv[4];
    {   const float4 t = ((const float4*)b2)[lane];
        bv[0] = t.x; bv[1] = t.y; bv[2] = t.z; bv[3] = t.w; }

    __syncthreads();

    const int w = blockIdx.x * WPB + wip;   // global warp id

    // Bresenham-balanced chunk list: 3 base chunks + possibly 1 tail chunk.
    const int fw    = (w * 17) / 37;
    const int fw1   = ((w + 1) * 17) / 37;
    const int nmine = 3 + (fw1 - fw);

    for (int k = 0; k < nmine; k++) {
        const int chunk = (k < 3) ? (w + k * NWARPS) : (BASE_CHUNKS + fw);
        const int b0 = chunk * S;
        float gate[S];

        // ---- per set: load, features, stage 1 (masked sum of relu(f@W1+b1)) ----
        #pragma unroll 1
        for (int s = 0; s < S; s++) {
            const int bset = b0 + s;
            int valid = 0;
            if (lane < P) {
                const int idx = bset * P + lane;
                valid = (mask[idx] != 0);
                if (valid) {
                    const float2 a  = ((const float2*)actor_locs)[bset];
                    const float2 pl = ((const float2*)player_locs)[idx];
                    const float2 fl = ((const float2*)flags)[idx];
                    const float dx = pl.x - a.x;
                    const float dy = pl.y - a.y;
                    const float d2 = fmaf(dx, dx, dy * dy);
                    const float dist = (d2 > 0.f) ? d2 * rsqrtf(d2) : 0.f;
                    const float ang  = fast_atan2(dy, dx);
                    sf0[wip][lane] = make_float4(dx, dy, dist, ang);
                    sf1[wip][lane] = fl;
                }
            }
            unsigned bal = __ballot_sync(0xffffffffu, valid);  // orders STS above
            const int cnt = __popc(bal);

            float ha = 0.f, hb = 0.f;
            while (bal) {
                const int p = __ffs(bal) - 1;
                bal &= bal - 1;                       // warp-uniform
                const float4 f0 = sf0[wip][p];        // broadcast LDS.128
                const float2 f1 = sf1[wip][p];        // broadcast LDS.64
                float va = b1a, vb = b1b;
                va = fmaf(f0.x, w1a[0], va);  vb = fmaf(f0.x, w1b[0], vb);
                va = fmaf(f0.y, w1a[1], va);  vb = fmaf(f0.y, w1b[1], vb);
                va = fmaf(f0.z, w1a[2], va);  vb = fmaf(f0.z, w1b[2], vb);
                va = fmaf(f0.w, w1a[3], va);  vb = fmaf(f0.w, w1b[3], vb);
                va = fmaf(f1.x, w1a[4], va);  vb = fmaf(f1.x, w1b[4], vb);
                va = fmaf(f1.y, w1a[5], va);  vb = fmaf(f1.y, w1b[5], vb);
                ha += fmaxf(va, 0.f);
                hb += fmaxf(vb, 0.f);
            }

            const float rc = (cnt > 0) ? __fdividef(1.0f, (float)cnt) : 0.0f;
            gate[s] = (cnt > 0) ? 1.0f : 0.0f;
            const float hha = ha * rc;
            const float hhb = hb * rc;
            shd[wip][lane     ][s] = make_float2(hha, hha);   // STS.64 duplicated
            shd[wip][lane + 32][s] = make_float2(hhb, hhb);
            __syncwarp();   // protect sf0/sf1 overwrite next set; shd before stage 2
        }

        // ---- stage 2: out[s] = h[s] @ W2 + gate[s]*b2 ----
        // acc[s][cp]: f32x2 over output comp-pairs; w pairs come free from LDS.128,
        // h duplicates come pre-staged from shd (broadcast LDS.128 x2 per j).
        unsigned long long acc[S][2];
        #pragma unroll
        for (int s = 0; s < S; s++) {
            acc[s][0] = pack2(bv[0] * gate[s], bv[1] * gate[s]);
            acc[s][1] = pack2(bv[2] * gate[s], bv[3] * gate[s]);
        }

        const float4* w2r = (const float4*)sW2;
        #pragma unroll
        for (int j = 0; j < HID; j++) {
            const float4 wv = w2r[j * (OUTD / 4) + lane];    // per-lane LDS.128
            const unsigned long long wp01 = pack2(wv.x, wv.y);  // natural reg pair
            const unsigned long long wp23 = pack2(wv.z, wv.w);  // natural reg pair
            const ulonglong2* hd = (const ulonglong2*)&shd[wip][j][0];
            const ulonglong2 hA = hd[0];   // (h0,h0),(h1,h1) broadcast LDS.128
            const ulonglong2 hB = hd[1];   // (h2,h2),(h3,h3) broadcast LDS.128
            acc[0][0] = fma2(hA.x, wp01, acc[0][0]);
            acc[0][1] = fma2(hA.x, wp23, acc[0][1]);
            acc[1][0] = fma2(hA.y, wp01, acc[1][0]);
            acc[1][1] = fma2(hA.y, wp23, acc[1][1]);
            acc[2][0] = fma2(hB.x, wp01, acc[2][0]);
            acc[2][1] = fma2(hB.x, wp23, acc[2][1]);
            acc[3][0] = fma2(hB.y, wp01, acc[3][0]);
            acc[3][1] = fma2(hB.y, wp23, acc[3][1]);
        }

        // acc[s] = (c0,c1),(c2,c3) consecutive regs -> STG.128 per set, no unpack
        float4* ov = (float4*)out;
        #pragma unroll
        for (int s = 0; s < S; s++) {
            float4 o;
            asm("mov.b64 {%0,%1}, %4;\n\t"
                "mov.b64 {%2,%3}, %5;"
                : "=f"(o.x), "=f"(o.y), "=f"(o.z), "=f"(o.w)
                : "l"(acc[s][0]), "l"(acc[s][1]));
            ov[(b0 + s) * (OUTD / 4) + lane] = o;
        }
    }
}

extern "C" void kernel_launch(void* const* d_in, const int* in_sizes, int n_in,
                              void* d_out, int out_size)
{
    const float* player_locs = (const float*)d_in[0];
    const float* actor_locs  = (const float*)d_in[1];
    const float* flags       = (const float*)d_in[2];
    const int*   mask        = (const int*)  d_in[3];
    const float* W1          = (const float*)d_in[4];
    const float* b1          = (const float*)d_in[5];
    const float* W2          = (const float*)d_in[6];
    const float* b2          = (const float*)d_in[7];
    float*       out         = (float*)d_out;

    set_encoder_kernel<<<GRID, THREADS>>>(player_locs, actor_locs, flags, mask,
                                          W1, b1, W2, b2, out);
}